// round 6
// baseline (speedup 1.0000x reference)
#include <cuda_runtime.h>

// y[o*48+p, n, m] = sum_i W0[p,i] * t4[o, (n-1)%56, m, i]
// t4[o, n', m, i] = sum_{j,k} xpad[o, j, n', m+k] * W1[j,k,i]  (pad 3 each side, width)
//
// 112 CTAs (one per (o, out-row n), single wave), 512 threads.
// t4 stored [i][m] stride 60 -> stage 3 reads it as float4 broadcasts.
// w0 padded [p][12] -> 3 LDS.128 per row.

#define NCH 12
#define WID 56
#define XSTRIDE 64          // xs row stride; data cols [4,60)
#define KS 7
#define NI 9
#define NP 48
#define T4S 60              // t4 row stride (words): mult of 4 (16B), 60%32=28 banks ok
#define W0S 12              // padded w0 row stride
#define THREADS 512

__global__ __launch_bounds__(THREADS, 1)
void fused_sepconv_kernel(const float* __restrict__ x,
                          const float* __restrict__ W0,
                          const float* __restrict__ W1,
                          float* __restrict__ out) {
    __shared__ alignas(16) float xs[NCH * XSTRIDE];   // 768
    __shared__ alignas(16) float w1s[NCH * KS * NI];  // 756
    __shared__ alignas(16) float w0p[NP * W0S];       // 576 (padded)
    __shared__ alignas(16) float t4s[NI * T4S];       // 540, [i][m]

    const int b = blockIdx.x;             // 0..111
    const int o = b / WID;
    const int n = b % WID;
    const int nin = (n + WID - 1) % WID;  // roll(+1) along height
    const int t = threadIdx.x;

    // ---- Phase 1: global loads issued first (max MLP) ----
    // [0,168): x quads (float4); [168,357): W1 quads (float4); [357,357+432): W0 scalar
    float4 v = make_float4(0.f, 0.f, 0.f, 0.f);
    float w0v = 0.f;
    if (t < 168) {
        int j  = t / 14;
        int q4 = t % 14;
        v = *(const float4*)&x[(((o * NCH + j) * WID + nin) * WID) + 4 * q4];
    } else if (t < 357) {
        v = *(const float4*)&W1[4 * (t - 168)];
    } else if (t < 357 + 144) {
        // 144 threads x 3 scalars each covers 432 W0 elements
        w0v = W0[t - 357];
    }
    float w0v2 = 0.f, w0v3 = 0.f;
    if (t >= 357 && t < 357 + 144) {
        w0v2 = W0[t - 357 + 144];
        w0v3 = W0[t - 357 + 288];
    }

    // Zero xs pad columns: cols [0,4) and [60,64) per channel = 24 float4 blocks
    if (t >= 488 && t < 512) {
        int s = t - 488;
        int j = s / 2;
        int side = s % 2;
        *(float4*)&xs[j * XSTRIDE + (side ? 60 : 0)] = make_float4(0.f, 0.f, 0.f, 0.f);
    }

    // Scatter to shared
    if (t < 168) {
        int j  = t / 14;
        int q4 = t % 14;
        *(float4*)&xs[j * XSTRIDE + 4 + 4 * q4] = v;
    } else if (t < 357) {
        *(float4*)&w1s[4 * (t - 168)] = v;
    } else if (t < 357 + 144) {
        int e0 = t - 357;
        int e1 = e0 + 144;
        int e2 = e0 + 288;
        w0p[(e0 / NI) * W0S + (e0 % NI)] = w0v;
        w0p[(e1 / NI) * W0S + (e1 % NI)] = w0v2;
        w0p[(e2 / NI) * W0S + (e2 % NI)] = w0v3;
    }
    // Zero the w0p padding lanes (i = 9..11) so stray FMA reads are harmless
    if (t < NP) {
        w0p[t * W0S + 9]  = 0.f;
        w0p[t * W0S + 10] = 0.f;
        w0p[t * W0S + 11] = 0.f;
    }

    __syncthreads();

    // ---- Stage 2: thread = (m-pair, i), i lane-fast ----
    // outputs (m0, m0+1) for one i; window union per j: xs[m0+1 .. m0+8].
    if (t < 28 * NI) {                    // 252 threads
        const int i    = t % NI;
        const int pair = t / NI;
        const int m0   = 2 * pair;

        float accA0 = 0.f, accA1 = 0.f;
        float accB0 = 0.f, accB1 = 0.f;

        #pragma unroll
        for (int j = 0; j < NCH; ++j) {
            float xw[8];
            #pragma unroll
            for (int kk = 0; kk < 8; ++kk)
                xw[kk] = xs[j * XSTRIDE + m0 + 1 + kk];

            #pragma unroll
            for (int k = 0; k < KS; ++k) {
                const float wv = w1s[(j * KS + k) * NI + i];
                if (k & 1) {
                    accA1 = fmaf(xw[k],     wv, accA1);
                    accB1 = fmaf(xw[k + 1], wv, accB1);
                } else {
                    accA0 = fmaf(xw[k],     wv, accA0);
                    accB0 = fmaf(xw[k + 1], wv, accB0);
                }
            }
        }
        // [i][m] layout; m0 even -> 8B-aligned float2 store
        float2 st = make_float2(accA0 + accA1, accB0 + accB1);
        *(float2*)&t4s[i * T4S + m0] = st;
    }

    __syncthreads();

    // ---- Stage 3: item = (mq, p); 672 items; vector loads + float4 store ----
    for (int item = t; item < 14 * NP; item += THREADS) {
        const int mq = item / NP;         // warp-uniform -> t4 float4 reads broadcast
        const int p  = item % NP;
        const int m0 = 4 * mq;

        // w0 row: 3 x LDS.128
        float4 wa = *(const float4*)&w0p[p * W0S + 0];
        float4 wb = *(const float4*)&w0p[p * W0S + 4];
        float  w8 = w0p[p * W0S + 8];

        float4 r = make_float4(0.f, 0.f, 0.f, 0.f);
        float* rp = (float*)&r;
        const float wscal[9] = {wa.x, wa.y, wa.z, wa.w, wb.x, wb.y, wb.z, wb.w, w8};

        #pragma unroll
        for (int i = 0; i < NI; ++i) {
            // t4 m-quad for channel i: one broadcast LDS.128
            float4 tq = *(const float4*)&t4s[i * T4S + m0];
            rp[0] = fmaf(tq.x, wscal[i], rp[0]);
            rp[1] = fmaf(tq.y, wscal[i], rp[1]);
            rp[2] = fmaf(tq.z, wscal[i], rp[2]);
            rp[3] = fmaf(tq.w, wscal[i], rp[3]);
        }
        *(float4*)&out[(((o * NP + p) * WID + n) * WID) + m0] = r;
    }
}

extern "C" void kernel_launch(void* const* d_in, const int* in_sizes, int n_in,
                              void* d_out, int out_size) {
    // Bind inputs by size: x=75264, W0=432, W1=756
    const float* x  = (const float*)d_in[0];
    const float* W0 = (const float*)d_in[1];
    const float* W1 = (const float*)d_in[2];
    for (int i = 0; i < n_in; ++i) {
        if (in_sizes[i] == 75264) x  = (const float*)d_in[i];
        else if (in_sizes[i] == 432) W0 = (const float*)d_in[i];
        else if (in_sizes[i] == 756) W1 = (const float*)d_in[i];
    }
    float* out = (float*)d_out;

    fused_sepconv_kernel<<<2 * WID, THREADS>>>(x, W0, W1, out);
}